// round 3
// baseline (speedup 1.0000x reference)
#include <cuda_runtime.h>
#include <cstdint>

// Problem constants (fixed-shape problem)
#define NN      50000
#define EE_MAX  800000
#define GG      128
#define DINF    200
#define DHF     128
#define NLAY    4
#define BN_EPS  1e-5f
#define OUTW    (DINF + NLAY * DHF)   // 712

// ---------------- scratch (device globals; no allocation allowed) ----------
__device__ float g_pooled0[NN * DINF];
__device__ float g_pooled [NN * DHF];
__device__ float g_mid    [NN * DHF];
__device__ float g_rep    [NN * DHF];
__device__ float g_h      [NN * DHF];
__device__ int   g_cnt    [2 * NN];      // [0,NN): hist, [NN,2NN): scatter cursor
__device__ int   g_rowptr [NN + 1];
__device__ int   g_colidx [EE_MAX];
__device__ int   g_gptr   [GG + 1];
__device__ float g_sum    [2 * NLAY][DHF];
__device__ float g_sumsq  [2 * NLAY][DHF];

// ---------------- CSR build ------------------------------------------------
__global__ void k_hist(const int* __restrict__ erow, int E) {
    int e = blockIdx.x * blockDim.x + threadIdx.x;
    if (e < E) atomicAdd(&g_cnt[erow[e]], 1);
}

// single-block scan, fully coalesced via big dynamic smem staging.
// Also zeroes the scatter cursors and the BN stat slots for this replay.
__global__ void k_scan_big() {
    extern __shared__ int sc[];            // [NN] + [1024] partials
    int* part = sc + NN;
    const int T = 1024;
    int t = threadIdx.x;

    if (t < DHF) {
        for (int l = 0; l < 2 * NLAY; l++) { g_sum[l][t] = 0.f; g_sumsq[l][t] = 0.f; }
    }
    for (int i = t; i < NN; i += T) {
        sc[i] = g_cnt[i];
        g_cnt[NN + i] = 0;
    }
    __syncthreads();

    const int C = (NN + T - 1) / T;
    int base = t * C;
    int s = 0;
    for (int j = 0; j < C; j++) {
        int i = base + j;
        if (i < NN) s += sc[i];
    }
    part[t] = s;
    __syncthreads();
    for (int off = 1; off < T; off <<= 1) {
        int v = (t >= off) ? part[t - off] : 0;
        __syncthreads();
        part[t] += v;
        __syncthreads();
    }
    int pre = (t > 0) ? part[t - 1] : 0;
    for (int j = 0; j < C; j++) {
        int i = base + j;
        if (i < NN) {
            int c = sc[i];
            sc[i] = pre;
            pre += c;
        }
    }
    __syncthreads();
    for (int i = t; i < NN; i += T) g_rowptr[i] = sc[i];
    if (t == T - 1) g_rowptr[NN] = pre;
}

__global__ void k_scatter(const int* __restrict__ erow, const int* __restrict__ ecol, int E) {
    int e = blockIdx.x * blockDim.x + threadIdx.x;
    if (e < E) {
        int r = erow[e];
        int p = g_rowptr[r] + atomicAdd(&g_cnt[NN + r], 1);
        g_colidx[p] = ecol[e];
    }
}

__global__ void k_gbounds(const int* __restrict__ gid) {
    int g = threadIdx.x;
    if (g <= GG) {
        int lo = 0, hi = NN;
        while (lo < hi) {
            int mid = (lo + hi) >> 1;
            if (gid[mid] < g) lo = mid + 1; else hi = mid;
        }
        g_gptr[g] = lo;
    }
}

// ---------------- SpMM (pull / CSR, one warp per destination node) ---------
template <int D4>
__global__ void k_spmm(const float* __restrict__ hin, float* __restrict__ pout,
                       const float* __restrict__ epsv, int li) {
    int wid  = blockIdx.x * 8 + (threadIdx.x >> 5);
    int lane = threadIdx.x & 31;
    if (wid >= NN) return;
    const int S = (D4 + 31) / 32;
    float se = 1.0f + epsv[li];

    const float4* selfr = (const float4*)hin + (size_t)wid * D4;
    float4 acc[S];
#pragma unroll
    for (int s = 0; s < S; s++) {
        int j = lane + 32 * s;
        if (j < D4) {
            float4 v = selfr[j];
            acc[s] = make_float4(v.x * se, v.y * se, v.z * se, v.w * se);
        } else {
            acc[s] = make_float4(0.f, 0.f, 0.f, 0.f);
        }
    }
    int e0 = g_rowptr[wid], e1 = g_rowptr[wid + 1];
    int e = e0;
    for (; e + 2 <= e1; e += 2) {
        int c0 = g_colidx[e];
        int c1 = g_colidx[e + 1];
        const float4* r0 = (const float4*)hin + (size_t)c0 * D4;
        const float4* r1 = (const float4*)hin + (size_t)c1 * D4;
#pragma unroll
        for (int s = 0; s < S; s++) {
            int j = lane + 32 * s;
            if (j < D4) {
                float4 v0 = r0[j];
                float4 v1 = r1[j];
                acc[s].x += v0.x + v1.x;
                acc[s].y += v0.y + v1.y;
                acc[s].z += v0.z + v1.z;
                acc[s].w += v0.w + v1.w;
            }
        }
    }
    if (e < e1) {
        int c = g_colidx[e];
        const float4* r = (const float4*)hin + (size_t)c * D4;
#pragma unroll
        for (int s = 0; s < S; s++) {
            int j = lane + 32 * s;
            if (j < D4) {
                float4 v = r[j];
                acc[s].x += v.x; acc[s].y += v.y; acc[s].z += v.z; acc[s].w += v.w;
            }
        }
    }
    float4* o = (float4*)pout + (size_t)wid * D4;
#pragma unroll
    for (int s = 0; s < S; s++) {
        int j = lane + 32 * s;
        if (j < D4) o[j] = acc[s];
    }
}

// ---------------- 3xTF32 tensor-core GEMM ---------------------------------
// C[M,128] = f(A[M,K]) @ W[K,128] + bias.
// If bnga != null: f(a)_k = relu(a * scale[k] + shift[k]) where scale/shift are
// computed in-kernel from (psum, psq, bnga, bnbe)  [replaces k_finalize].
// Epilogue: column sum / sumsq accumulated into osum/osumsq.

__device__ __forceinline__ uint32_t f2tf32(float v) {
    uint32_t r;
    asm("cvt.rna.tf32.f32 %0, %1;" : "=r"(r) : "f"(v));
    return r;
}

__device__ __forceinline__ void mma8(float* c, const uint32_t* a, const uint32_t* b) {
    asm volatile(
        "mma.sync.aligned.m16n8k8.row.col.f32.tf32.tf32.f32 "
        "{%0,%1,%2,%3}, {%4,%5,%6,%7}, {%8,%9}, {%0,%1,%2,%3};"
        : "+f"(c[0]), "+f"(c[1]), "+f"(c[2]), "+f"(c[3])
        : "r"(a[0]), "r"(a[1]), "r"(a[2]), "r"(a[3]), "r"(b[0]), "r"(b[1]));
}

__global__ __launch_bounds__(512, 1)
void k_gemm_tc(const float* __restrict__ A, const float* __restrict__ W,
               const float* __restrict__ bias, float* __restrict__ C,
               int M, int K,
               const float* __restrict__ bnga, const float* __restrict__ bnbe,
               const float* __restrict__ psum, const float* __restrict__ psq,
               float* __restrict__ osum, float* __restrict__ osumsq) {
    // pad 136: 136 % 32 == 8 -> mma LDS bank = 8*tq + gid (+const): permutation
    __shared__ uint32_t ash[16][136], asl[16][136];
    __shared__ uint32_t wsh[16][136], wsl[16][136];
    __shared__ float strs[DHF], strh[DHF];

    const int tid  = threadIdx.x;
    const int lane = tid & 31;
    const int wid  = tid >> 5;
    const int wr   = wid >> 2;   // 0..3 (row group of 32)
    const int wc   = wid & 3;    // 0..3 (col group of 32)
    const int gid  = lane >> 2;  // 0..7
    const int tq   = lane & 3;   // 0..3
    const int row0 = blockIdx.x * 128;

    const int ar = tid & 127;    // A row within tile / W column
    const int kg = tid >> 7;     // 0..3 -> kk = 4*kg + j

    const bool use_bn = (bnga != nullptr);
    if (use_bn) {
        if (tid < DHF) {
            const float invN = 1.0f / NN;
            float m = psum[tid] * invN;
            float v = psq[tid] * invN - m * m;
            float rs = rsqrtf(v + BN_EPS);
            float sc = bnga[tid] * rs;
            strs[tid] = sc;
            strh[tid] = bnbe[tid] - m * sc;
        }
        __syncthreads();
    }

    float acc[2][4][4];
#pragma unroll
    for (int mt = 0; mt < 2; mt++)
#pragma unroll
        for (int nt = 0; nt < 4; nt++)
#pragma unroll
            for (int j = 0; j < 4; j++) acc[mt][nt][j] = 0.f;

    const int T = (K + 15) >> 4;
    const int gr = row0 + ar;
    const bool rok = (gr < M);

    float4 va;
    float wv[4];

    // ---- prefetch tile 0 ----
    {
        int gk0 = 4 * kg;
        va = make_float4(0.f, 0.f, 0.f, 0.f);
        if (rok && gk0 < K) va = *(const float4*)&A[(size_t)gr * K + gk0];
#pragma unroll
        for (int j = 0; j < 4; j++) {
            int kw = 4 * kg + j;
            wv[j] = (kw < K) ? W[(size_t)kw * 128 + ar] : 0.f;
        }
    }

    for (int t = 0; t < T; t++) {
        int k0 = t * 16;
        // ---- stage current tile into smem (hi/lo tf32 split) ----
        {
            float a4[4] = {va.x, va.y, va.z, va.w};
#pragma unroll
            for (int j = 0; j < 4; j++) {
                float v = a4[j];
                if (use_bn && rok) {
                    int gk = k0 + 4 * kg + j;
                    v = (gk < K) ? fmaxf(v * strs[gk] + strh[gk], 0.f) : 0.f;
                }
                uint32_t hi = f2tf32(v);
                ash[4 * kg + j][ar] = hi;
                asl[4 * kg + j][ar] = f2tf32(v - __uint_as_float(hi));
                uint32_t whi = f2tf32(wv[j]);
                wsh[4 * kg + j][ar] = whi;
                wsl[4 * kg + j][ar] = f2tf32(wv[j] - __uint_as_float(whi));
            }
        }
        __syncthreads();

        // ---- prefetch next tile ----
        if (t + 1 < T) {
            int kb = (t + 1) * 16;
            int gk0 = kb + 4 * kg;
            va = make_float4(0.f, 0.f, 0.f, 0.f);
            if (rok && gk0 < K) va = *(const float4*)&A[(size_t)gr * K + gk0];
#pragma unroll
            for (int j = 0; j < 4; j++) {
                int kw = kb + 4 * kg + j;
                wv[j] = (kw < K) ? W[(size_t)kw * 128 + ar] : 0.f;
            }
        }

        // ---- mma over the resident tile ----
#pragma unroll
        for (int ks = 0; ks < 16; ks += 8) {
            uint32_t bh[4][2], bl[4][2];
#pragma unroll
            for (int nt = 0; nt < 4; nt++) {
                int col = wc * 32 + nt * 8 + gid;
                bh[nt][0] = wsh[ks + tq][col];
                bh[nt][1] = wsh[ks + tq + 4][col];
                bl[nt][0] = wsl[ks + tq][col];
                bl[nt][1] = wsl[ks + tq + 4][col];
            }
#pragma unroll
            for (int mt = 0; mt < 2; mt++) {
                int r0 = wr * 32 + mt * 16;
                uint32_t ah[4], al[4];
                ah[0] = ash[ks + tq][r0 + gid];
                ah[1] = ash[ks + tq][r0 + gid + 8];
                ah[2] = ash[ks + tq + 4][r0 + gid];
                ah[3] = ash[ks + tq + 4][r0 + gid + 8];
                al[0] = asl[ks + tq][r0 + gid];
                al[1] = asl[ks + tq][r0 + gid + 8];
                al[2] = asl[ks + tq + 4][r0 + gid];
                al[3] = asl[ks + tq + 4][r0 + gid + 8];
#pragma unroll
                for (int nt = 0; nt < 4; nt++) {
                    mma8(acc[mt][nt], ah, bh[nt]);   // hi*hi
                    mma8(acc[mt][nt], al, bh[nt]);   // lo*hi
                    mma8(acc[mt][nt], ah, bl[nt]);   // hi*lo
                }
            }
        }
        __syncthreads();
    }

    // ---- epilogue: bias, store, column stats ----
    float cs[4][2], cq[4][2];
#pragma unroll
    for (int nt = 0; nt < 4; nt++)
#pragma unroll
        for (int j = 0; j < 2; j++) { cs[nt][j] = 0.f; cq[nt][j] = 0.f; }

#pragma unroll
    for (int mt = 0; mt < 2; mt++) {
        int rbase = row0 + wr * 32 + mt * 16;
#pragma unroll
        for (int nt = 0; nt < 4; nt++) {
            int colb = wc * 32 + nt * 8 + 2 * tq;
            float b0 = bias[colb], b1 = bias[colb + 1];
            int r1 = rbase + gid;
            int r2 = rbase + gid + 8;
            if (r1 < M) {
                float v0 = acc[mt][nt][0] + b0;
                float v1 = acc[mt][nt][1] + b1;
                *(float2*)&C[(size_t)r1 * 128 + colb] = make_float2(v0, v1);
                cs[nt][0] += v0; cq[nt][0] += v0 * v0;
                cs[nt][1] += v1; cq[nt][1] += v1 * v1;
            }
            if (r2 < M) {
                float v0 = acc[mt][nt][2] + b0;
                float v1 = acc[mt][nt][3] + b1;
                *(float2*)&C[(size_t)r2 * 128 + colb] = make_float2(v0, v1);
                cs[nt][0] += v0; cq[nt][0] += v0 * v0;
                cs[nt][1] += v1; cq[nt][1] += v1 * v1;
            }
        }
    }
#pragma unroll
    for (int nt = 0; nt < 4; nt++)
#pragma unroll
        for (int j = 0; j < 2; j++) {
            float s = cs[nt][j], q = cq[nt][j];
            s += __shfl_xor_sync(0xffffffffu, s, 4);
            s += __shfl_xor_sync(0xffffffffu, s, 8);
            s += __shfl_xor_sync(0xffffffffu, s, 16);
            q += __shfl_xor_sync(0xffffffffu, q, 4);
            q += __shfl_xor_sync(0xffffffffu, q, 8);
            q += __shfl_xor_sync(0xffffffffu, q, 16);
            if (gid == 0) {
                int col = wc * 32 + nt * 8 + 2 * tq + j;
                atomicAdd(&osum[col], s);
                atomicAdd(&osumsq[col], q);
            }
        }
}

// ---------------- fused BN + ReLU + graph pool (block = graph) -------------
__global__ void k_bnpool(const float* __restrict__ rep, float* __restrict__ h,
                         float* __restrict__ out, int off,
                         const float* __restrict__ gamma, const float* __restrict__ beta,
                         int slot, int write_h) {
    int g = blockIdx.x;
    int c = threadIdx.x;      // 128 threads
    const float invN = 1.0f / NN;
    float m = g_sum[slot][c] * invN;
    float v = g_sumsq[slot][c] * invN - m * m;
    float rs = rsqrtf(v + BN_EPS);
    float sc = gamma[c] * rs;
    float sh = beta[c] - m * sc;

    float acc = 0.f;
    int i0 = g_gptr[g], i1 = g_gptr[g + 1];
#pragma unroll 2
    for (int i = i0; i < i1; i++) {
        float x = rep[(size_t)i * DHF + c];
        x = fmaxf(x * sc + sh, 0.f);
        if (write_h) h[(size_t)i * DHF + c] = x;
        acc += x;
    }
    out[(size_t)g * OUTW + off + c] = acc;
}

// graph sum pooling for the raw input x (D = 200)
__global__ void k_poolx(const float* __restrict__ src, float* __restrict__ out) {
    int g = blockIdx.x;
    int c = threadIdx.x;
    if (c >= DINF) return;
    float s = 0.f;
    int i0 = g_gptr[g], i1 = g_gptr[g + 1];
#pragma unroll 2
    for (int i = i0; i < i1; i++) s += src[(size_t)i * DINF + c];
    out[(size_t)g * OUTW + c] = s;
}

// ---------------- launch ---------------------------------------------------
extern "C" void kernel_launch(void* const* d_in, const int* in_sizes, int n_in,
                              void* d_out, int out_size) {
    const float* x     = (const float*)d_in[0];
    const int*   erow  = (const int*)d_in[1];
    const int*   ecol  = (const int*)d_in[2];
    const int*   gid   = (const int*)d_in[3];
    const float* eps   = (const float*)d_in[4];
    const float* w1_0  = (const float*)d_in[5];
    const float* b1_0  = (const float*)d_in[6];
    const float* g1_0  = (const float*)d_in[7];
    const float* be1_0 = (const float*)d_in[8];
    const float* w2_0  = (const float*)d_in[9];
    const float* b2_0  = (const float*)d_in[10];
    const float* gbn_0 = (const float*)d_in[11];
    const float* bbn_0 = (const float*)d_in[12];
    const float* w1_r  = (const float*)d_in[13];
    const float* b1_r  = (const float*)d_in[14];
    const float* g1_r  = (const float*)d_in[15];
    const float* be1_r = (const float*)d_in[16];
    const float* w2_r  = (const float*)d_in[17];
    const float* b2_r  = (const float*)d_in[18];
    const float* gbn_r = (const float*)d_in[19];
    const float* bbn_r = (const float*)d_in[20];
    float* out = (float*)d_out;

    int E = in_sizes[1];

    float *pooled0, *pooled, *mid, *rep, *h, *sumb, *sumsqb;
    int *cnt;
    cudaGetSymbolAddress((void**)&pooled0, g_pooled0);
    cudaGetSymbolAddress((void**)&pooled,  g_pooled);
    cudaGetSymbolAddress((void**)&mid,     g_mid);
    cudaGetSymbolAddress((void**)&rep,     g_rep);
    cudaGetSymbolAddress((void**)&h,       g_h);
    cudaGetSymbolAddress((void**)&sumb,    g_sum);
    cudaGetSymbolAddress((void**)&sumsqb,  g_sumsq);
    cudaGetSymbolAddress((void**)&cnt,     g_cnt);

    const int scan_smem = (NN + 1024) * (int)sizeof(int);
    cudaFuncSetAttribute(k_scan_big, cudaFuncAttributeMaxDynamicSharedMemorySize, scan_smem);

    // ---- CSR build ----
    cudaMemsetAsync(cnt, 0, NN * sizeof(int));
    k_hist<<<(E + 255) / 256, 256>>>(erow, E);
    k_scan_big<<<1, 1024, scan_smem>>>();          // + zero cursors & BN stats
    k_scatter<<<(E + 255) / 256, 256>>>(erow, ecol, E);

    const int spmm_blocks = (NN + 7) / 8;
    const int gemm_blocks = (NN + 127) / 128;

    for (int l = 0; l < NLAY; l++) {
        const float *wa, *ba, *ga, *bea, *wb, *bb, *gb, *bbb;
        const float* Ain;
        int K1;
        if (l == 0) {
            k_spmm<DINF / 4><<<spmm_blocks, 256>>>(x, pooled0, eps, 0);
            Ain = pooled0; K1 = DINF;
            wa = w1_0; ba = b1_0; ga = g1_0; bea = be1_0;
            wb = w2_0; bb = b2_0; gb = gbn_0; bbb = bbn_0;
        } else {
            k_spmm<DHF / 4><<<spmm_blocks, 256>>>(h, pooled, eps, l);
            Ain = pooled; K1 = DHF;
            int o2 = (l - 1) * DHF * DHF, o1 = (l - 1) * DHF;
            wa = w1_r + o2; ba = b1_r + o1; ga = g1_r + o1; bea = be1_r + o1;
            wb = w2_r + o2; bb = b2_r + o1; gb = gbn_r + o1; bbb = bbn_r + o1;
        }

        // GEMM1: plain A
        k_gemm_tc<<<gemm_blocks, 512>>>(Ain, wa, ba, mid, NN, K1,
                                        nullptr, nullptr, nullptr, nullptr,
                                        sumb + (2 * l) * DHF, sumsqb + (2 * l) * DHF);
        // GEMM2: BN+ReLU on A computed in-kernel from slot-2l stats
        k_gemm_tc<<<gemm_blocks, 512>>>(mid, wb, bb, rep, NN, DHF,
                                        ga, bea, sumb + (2 * l) * DHF, sumsqb + (2 * l) * DHF,
                                        sumb + (2 * l + 1) * DHF, sumsqb + (2 * l + 1) * DHF);

        if (l == 0) k_gbounds<<<1, 256>>>(gid);

        // fused BN + ReLU + pool (slot 2l+1 stats); h written for layers 0..2
        k_bnpool<<<GG, DHF>>>(rep, h, out, DINF + l * DHF, gb, bbb,
                              2 * l + 1, (l < NLAY - 1) ? 1 : 0);
    }

    // pooled x -> out[:, 0:200]
    k_poolx<<<GG, 256>>>(x, out);
}

// round 4
// speedup vs baseline: 1.2582x; 1.2582x over previous
#include <cuda_runtime.h>
#include <cstdint>

// Problem constants (fixed-shape problem)
#define NN      50000
#define EE_MAX  800000
#define GG      128
#define DINF    200
#define DHF     128
#define NLAY    4
#define BN_EPS  1e-5f
#define OUTW    (DINF + NLAY * DHF)   // 712
#define BNP_ROWS 128                  // rows per pooling chunk-block

// ---------------- scratch (device globals; no allocation allowed) ----------
__device__ float g_pooled0[NN * DINF];
__device__ float g_pooled [NN * DHF];
__device__ float g_mid    [NN * DHF];
__device__ float g_rep    [NN * DHF];
__device__ float g_h      [NN * DHF];
__device__ int   g_cnt    [2 * NN];      // [0,NN): hist, [NN,2NN): scatter cursor
__device__ int   g_rowptr [NN + 1];
__device__ int   g_colidx [EE_MAX];
__device__ float g_sum    [2 * NLAY][DHF];
__device__ float g_sumsq  [2 * NLAY][DHF];

// ---------------- CSR build ------------------------------------------------
__global__ void k_hist(const int* __restrict__ erow, int E) {
    int e = blockIdx.x * blockDim.x + threadIdx.x;
    if (e < E) atomicAdd(&g_cnt[erow[e]], 1);
}

// single-block scan, coalesced via big dynamic smem staging.
// Also zeroes the scatter cursors and the BN stat slots for this replay.
__global__ void k_scan_big() {
    extern __shared__ int sc[];            // [NN] + [1024] partials
    int* part = sc + NN;
    const int T = 1024;
    int t = threadIdx.x;

    if (t < DHF) {
        for (int l = 0; l < 2 * NLAY; l++) { g_sum[l][t] = 0.f; g_sumsq[l][t] = 0.f; }
    }
    for (int i = t; i < NN; i += T) {
        sc[i] = g_cnt[i];
        g_cnt[NN + i] = 0;
    }
    __syncthreads();

    const int C = (NN + T - 1) / T;
    int base = t * C;
    int s = 0;
    for (int j = 0; j < C; j++) {
        int i = base + j;
        if (i < NN) s += sc[i];
    }
    part[t] = s;
    __syncthreads();
    for (int off = 1; off < T; off <<= 1) {
        int v = (t >= off) ? part[t - off] : 0;
        __syncthreads();
        part[t] += v;
        __syncthreads();
    }
    int pre = (t > 0) ? part[t - 1] : 0;
    for (int j = 0; j < C; j++) {
        int i = base + j;
        if (i < NN) {
            int c = sc[i];
            sc[i] = pre;
            pre += c;
        }
    }
    __syncthreads();
    for (int i = t; i < NN; i += T) g_rowptr[i] = sc[i];
    if (t == T - 1) g_rowptr[NN] = pre;
}

__global__ void k_scatter(const int* __restrict__ erow, const int* __restrict__ ecol, int E) {
    int e = blockIdx.x * blockDim.x + threadIdx.x;
    if (e < E) {
        int r = erow[e];
        int p = g_rowptr[r] + atomicAdd(&g_cnt[NN + r], 1);
        g_colidx[p] = ecol[e];
    }
}

// ---------------- SpMM (pull / CSR, one warp per destination node) ---------
template <int D4>
__global__ void k_spmm(const float* __restrict__ hin, float* __restrict__ pout,
                       const float* __restrict__ epsv, int li) {
    int wid  = blockIdx.x * 8 + (threadIdx.x >> 5);
    int lane = threadIdx.x & 31;
    if (wid >= NN) return;
    const int S = (D4 + 31) / 32;
    float se = 1.0f + epsv[li];

    const float4* selfr = (const float4*)hin + (size_t)wid * D4;
    float4 acc[S];
#pragma unroll
    for (int s = 0; s < S; s++) {
        int j = lane + 32 * s;
        if (j < D4) {
            float4 v = selfr[j];
            acc[s] = make_float4(v.x * se, v.y * se, v.z * se, v.w * se);
        } else {
            acc[s] = make_float4(0.f, 0.f, 0.f, 0.f);
        }
    }
    int e0 = g_rowptr[wid], e1 = g_rowptr[wid + 1];
    int e = e0;
    for (; e + 2 <= e1; e += 2) {
        int c0 = g_colidx[e];
        int c1 = g_colidx[e + 1];
        const float4* r0 = (const float4*)hin + (size_t)c0 * D4;
        const float4* r1 = (const float4*)hin + (size_t)c1 * D4;
#pragma unroll
        for (int s = 0; s < S; s++) {
            int j = lane + 32 * s;
            if (j < D4) {
                float4 v0 = r0[j];
                float4 v1 = r1[j];
                acc[s].x += v0.x + v1.x;
                acc[s].y += v0.y + v1.y;
                acc[s].z += v0.z + v1.z;
                acc[s].w += v0.w + v1.w;
            }
        }
    }
    if (e < e1) {
        int c = g_colidx[e];
        const float4* r = (const float4*)hin + (size_t)c * D4;
#pragma unroll
        for (int s = 0; s < S; s++) {
            int j = lane + 32 * s;
            if (j < D4) {
                float4 v = r[j];
                acc[s].x += v.x; acc[s].y += v.y; acc[s].z += v.z; acc[s].w += v.w;
            }
        }
    }
    float4* o = (float4*)pout + (size_t)wid * D4;
#pragma unroll
    for (int s = 0; s < S; s++) {
        int j = lane + 32 * s;
        if (j < D4) o[j] = acc[s];
    }
}

// ---------------- 3xTF32 tensor-core GEMM ---------------------------------
__device__ __forceinline__ uint32_t f2tf32(float v) {
    uint32_t r;
    asm("cvt.rna.tf32.f32 %0, %1;" : "=r"(r) : "f"(v));
    return r;
}

__device__ __forceinline__ void mma8(float* c, const uint32_t* a, const uint32_t* b) {
    asm volatile(
        "mma.sync.aligned.m16n8k8.row.col.f32.tf32.tf32.f32 "
        "{%0,%1,%2,%3}, {%4,%5,%6,%7}, {%8,%9}, {%0,%1,%2,%3};"
        : "+f"(c[0]), "+f"(c[1]), "+f"(c[2]), "+f"(c[3])
        : "r"(a[0]), "r"(a[1]), "r"(a[2]), "r"(a[3]), "r"(b[0]), "r"(b[1]));
}

__global__ __launch_bounds__(512, 2)
void k_gemm_tc(const float* __restrict__ A, const float* __restrict__ W,
               const float* __restrict__ bias, float* __restrict__ C,
               int M, int K,
               const float* __restrict__ bnga, const float* __restrict__ bnbe,
               const float* __restrict__ psum, const float* __restrict__ psq,
               float* __restrict__ osum, float* __restrict__ osumsq) {
    // pad 136: 136 % 32 == 8 -> mma LDS bank = 8*tq + gid (+const): permutation
    __shared__ uint32_t ash[16][136], asl[16][136];
    __shared__ uint32_t wsh[16][136], wsl[16][136];
    __shared__ float strs[DHF], strh[DHF];

    const int tid  = threadIdx.x;
    const int lane = tid & 31;
    const int wid  = tid >> 5;
    const int wr   = wid >> 2;
    const int wc   = wid & 3;
    const int gid  = lane >> 2;
    const int tq   = lane & 3;
    const int row0 = blockIdx.x * 128;

    const int ar = tid & 127;    // A row within tile / W column
    const int kg = tid >> 7;     // 0..3 -> kk = 4*kg + j

    const bool use_bn = (bnga != nullptr);
    if (use_bn) {
        if (tid < DHF) {
            const float invN = 1.0f / NN;
            float m = psum[tid] * invN;
            float v = psq[tid] * invN - m * m;
            float rs = rsqrtf(v + BN_EPS);
            float sc = bnga[tid] * rs;
            strs[tid] = sc;
            strh[tid] = bnbe[tid] - m * sc;
        }
        __syncthreads();
    }

    float acc[2][4][4];
#pragma unroll
    for (int mt = 0; mt < 2; mt++)
#pragma unroll
        for (int nt = 0; nt < 4; nt++)
#pragma unroll
            for (int j = 0; j < 4; j++) acc[mt][nt][j] = 0.f;

    const int T = (K + 15) >> 4;
    const int gr = row0 + ar;
    const bool rok = (gr < M);

    float4 va;
    float wv[4];

    {
        int gk0 = 4 * kg;
        va = make_float4(0.f, 0.f, 0.f, 0.f);
        if (rok && gk0 < K) va = *(const float4*)&A[(size_t)gr * K + gk0];
#pragma unroll
        for (int j = 0; j < 4; j++) {
            int kw = 4 * kg + j;
            wv[j] = (kw < K) ? W[(size_t)kw * 128 + ar] : 0.f;
        }
    }

    for (int t = 0; t < T; t++) {
        int k0 = t * 16;
        {
            float a4[4] = {va.x, va.y, va.z, va.w};
#pragma unroll
            for (int j = 0; j < 4; j++) {
                float v = a4[j];
                if (use_bn && rok) {
                    int gk = k0 + 4 * kg + j;
                    v = (gk < K) ? fmaxf(v * strs[gk] + strh[gk], 0.f) : 0.f;
                }
                uint32_t hi = f2tf32(v);
                ash[4 * kg + j][ar] = hi;
                asl[4 * kg + j][ar] = f2tf32(v - __uint_as_float(hi));
                uint32_t whi = f2tf32(wv[j]);
                wsh[4 * kg + j][ar] = whi;
                wsl[4 * kg + j][ar] = f2tf32(wv[j] - __uint_as_float(whi));
            }
        }
        __syncthreads();

        if (t + 1 < T) {
            int kb = (t + 1) * 16;
            int gk0 = kb + 4 * kg;
            va = make_float4(0.f, 0.f, 0.f, 0.f);
            if (rok && gk0 < K) va = *(const float4*)&A[(size_t)gr * K + gk0];
#pragma unroll
            for (int j = 0; j < 4; j++) {
                int kw = kb + 4 * kg + j;
                wv[j] = (kw < K) ? W[(size_t)kw * 128 + ar] : 0.f;
            }
        }

#pragma unroll
        for (int ks = 0; ks < 16; ks += 8) {
            uint32_t bh[4][2], bl[4][2];
#pragma unroll
            for (int nt = 0; nt < 4; nt++) {
                int col = wc * 32 + nt * 8 + gid;
                bh[nt][0] = wsh[ks + tq][col];
                bh[nt][1] = wsh[ks + tq + 4][col];
                bl[nt][0] = wsl[ks + tq][col];
                bl[nt][1] = wsl[ks + tq + 4][col];
            }
#pragma unroll
            for (int mt = 0; mt < 2; mt++) {
                int r0 = wr * 32 + mt * 16;
                uint32_t ah[4], al[4];
                ah[0] = ash[ks + tq][r0 + gid];
                ah[1] = ash[ks + tq][r0 + gid + 8];
                ah[2] = ash[ks + tq + 4][r0 + gid];
                ah[3] = ash[ks + tq + 4][r0 + gid + 8];
                al[0] = asl[ks + tq][r0 + gid];
                al[1] = asl[ks + tq][r0 + gid + 8];
                al[2] = asl[ks + tq + 4][r0 + gid];
                al[3] = asl[ks + tq + 4][r0 + gid + 8];
#pragma unroll
                for (int nt = 0; nt < 4; nt++) {
                    mma8(acc[mt][nt], ah, bh[nt]);   // hi*hi
                    mma8(acc[mt][nt], al, bh[nt]);   // lo*hi
                    mma8(acc[mt][nt], ah, bl[nt]);   // hi*lo
                }
            }
        }
        __syncthreads();
    }

    // ---- epilogue: bias, store, column stats ----
    float cs[4][2], cq[4][2];
#pragma unroll
    for (int nt = 0; nt < 4; nt++)
#pragma unroll
        for (int j = 0; j < 2; j++) { cs[nt][j] = 0.f; cq[nt][j] = 0.f; }

#pragma unroll
    for (int mt = 0; mt < 2; mt++) {
        int rbase = row0 + wr * 32 + mt * 16;
#pragma unroll
        for (int nt = 0; nt < 4; nt++) {
            int colb = wc * 32 + nt * 8 + 2 * tq;
            float b0 = bias[colb], b1 = bias[colb + 1];
            int r1 = rbase + gid;
            int r2 = rbase + gid + 8;
            if (r1 < M) {
                float v0 = acc[mt][nt][0] + b0;
                float v1 = acc[mt][nt][1] + b1;
                *(float2*)&C[(size_t)r1 * 128 + colb] = make_float2(v0, v1);
                cs[nt][0] += v0; cq[nt][0] += v0 * v0;
                cs[nt][1] += v1; cq[nt][1] += v1 * v1;
            }
            if (r2 < M) {
                float v0 = acc[mt][nt][2] + b0;
                float v1 = acc[mt][nt][3] + b1;
                *(float2*)&C[(size_t)r2 * 128 + colb] = make_float2(v0, v1);
                cs[nt][0] += v0; cq[nt][0] += v0 * v0;
                cs[nt][1] += v1; cq[nt][1] += v1 * v1;
            }
        }
    }
#pragma unroll
    for (int nt = 0; nt < 4; nt++)
#pragma unroll
        for (int j = 0; j < 2; j++) {
            float s = cs[nt][j], q = cq[nt][j];
            s += __shfl_xor_sync(0xffffffffu, s, 4);
            s += __shfl_xor_sync(0xffffffffu, s, 8);
            s += __shfl_xor_sync(0xffffffffu, s, 16);
            q += __shfl_xor_sync(0xffffffffu, q, 4);
            q += __shfl_xor_sync(0xffffffffu, q, 8);
            q += __shfl_xor_sync(0xffffffffu, q, 16);
            if (gid == 0) {
                int col = wc * 32 + nt * 8 + 2 * tq + j;
                atomicAdd(&osum[col], s);
                atomicAdd(&osumsq[col], q);
            }
        }
}

// ------ fused BN + ReLU + graph pool, CHUNK-PARALLEL (block = 128 rows) ----
// graph_ids sorted -> each chunk spans few graphs; flush partial sums with
// one atomicAdd per (boundary, column). out must be pre-zeroed.
__global__ void k_bnpool(const float* __restrict__ rep, float* __restrict__ h,
                         float* __restrict__ out, int off,
                         const float* __restrict__ gamma, const float* __restrict__ beta,
                         const int* __restrict__ gids, int slot, int write_h) {
    int c = threadIdx.x;                  // 128 threads = columns
    int r0 = blockIdx.x * BNP_ROWS;
    int r1 = min(r0 + BNP_ROWS, NN);
    const float invN = 1.0f / NN;
    float m = g_sum[slot][c] * invN;
    float v = g_sumsq[slot][c] * invN - m * m;
    float sc = gamma[c] * rsqrtf(v + BN_EPS);
    float sh = beta[c] - m * sc;

    int curg = gids[r0];
    float acc = 0.f;
    for (int r = r0; r < r1; r++) {
        int gr = gids[r];
        if (gr != curg) {
            atomicAdd(&out[(size_t)curg * OUTW + off + c], acc);
            acc = 0.f;
            curg = gr;
        }
        float xv = fmaxf(rep[(size_t)r * DHF + c] * sc + sh, 0.f);
        if (write_h) h[(size_t)r * DHF + c] = xv;
        acc += xv;
    }
    atomicAdd(&out[(size_t)curg * OUTW + off + c], acc);
}

// chunk-parallel pooling of raw x (D=200) into out[:, 0:200]
__global__ void k_poolx(const float* __restrict__ src, float* __restrict__ out,
                        const int* __restrict__ gids) {
    int c = threadIdx.x;                  // 256 threads, guard to 200
    if (c >= DINF) return;
    int r0 = blockIdx.x * BNP_ROWS;
    int r1 = min(r0 + BNP_ROWS, NN);
    int curg = gids[r0];
    float acc = 0.f;
    for (int r = r0; r < r1; r++) {
        int gr = gids[r];
        if (gr != curg) {
            atomicAdd(&out[(size_t)curg * OUTW + c], acc);
            acc = 0.f;
            curg = gr;
        }
        acc += src[(size_t)r * DINF + c];
    }
    atomicAdd(&out[(size_t)curg * OUTW + c], acc);
}

// ---------------- launch ---------------------------------------------------
extern "C" void kernel_launch(void* const* d_in, const int* in_sizes, int n_in,
                              void* d_out, int out_size) {
    const float* x     = (const float*)d_in[0];
    const int*   erow  = (const int*)d_in[1];
    const int*   ecol  = (const int*)d_in[2];
    const int*   gid   = (const int*)d_in[3];
    const float* eps   = (const float*)d_in[4];
    const float* w1_0  = (const float*)d_in[5];
    const float* b1_0  = (const float*)d_in[6];
    const float* g1_0  = (const float*)d_in[7];
    const float* be1_0 = (const float*)d_in[8];
    const float* w2_0  = (const float*)d_in[9];
    const float* b2_0  = (const float*)d_in[10];
    const float* gbn_0 = (const float*)d_in[11];
    const float* bbn_0 = (const float*)d_in[12];
    const float* w1_r  = (const float*)d_in[13];
    const float* b1_r  = (const float*)d_in[14];
    const float* g1_r  = (const float*)d_in[15];
    const float* be1_r = (const float*)d_in[16];
    const float* w2_r  = (const float*)d_in[17];
    const float* b2_r  = (const float*)d_in[18];
    const float* gbn_r = (const float*)d_in[19];
    const float* bbn_r = (const float*)d_in[20];
    float* out = (float*)d_out;

    int E = in_sizes[1];

    float *pooled0, *pooled, *mid, *rep, *h, *sumb, *sumsqb;
    int *cnt;
    cudaGetSymbolAddress((void**)&pooled0, g_pooled0);
    cudaGetSymbolAddress((void**)&pooled,  g_pooled);
    cudaGetSymbolAddress((void**)&mid,     g_mid);
    cudaGetSymbolAddress((void**)&rep,     g_rep);
    cudaGetSymbolAddress((void**)&h,       g_h);
    cudaGetSymbolAddress((void**)&sumb,    g_sum);
    cudaGetSymbolAddress((void**)&sumsqb,  g_sumsq);
    cudaGetSymbolAddress((void**)&cnt,     g_cnt);

    const int scan_smem = (NN + 1024) * (int)sizeof(int);
    cudaFuncSetAttribute(k_scan_big, cudaFuncAttributeMaxDynamicSharedMemorySize, scan_smem);

    // ---- CSR build + output zeroing ----
    cudaMemsetAsync(cnt, 0, NN * sizeof(int));
    cudaMemsetAsync(out, 0, (size_t)out_size * sizeof(float));
    k_hist<<<(E + 255) / 256, 256>>>(erow, E);
    k_scan_big<<<1, 1024, scan_smem>>>();          // + zero cursors & BN stats
    k_scatter<<<(E + 255) / 256, 256>>>(erow, ecol, E);

    const int spmm_blocks = (NN + 7) / 8;
    const int gemm_blocks = (NN + 127) / 128;
    const int pool_blocks = (NN + BNP_ROWS - 1) / BNP_ROWS;

    for (int l = 0; l < NLAY; l++) {
        const float *wa, *ba, *ga, *bea, *wb, *bb, *gb, *bbb;
        const float* Ain;
        int K1;
        if (l == 0) {
            k_spmm<DINF / 4><<<spmm_blocks, 256>>>(x, pooled0, eps, 0);
            Ain = pooled0; K1 = DINF;
            wa = w1_0; ba = b1_0; ga = g1_0; bea = be1_0;
            wb = w2_0; bb = b2_0; gb = gbn_0; bbb = bbn_0;
        } else {
            k_spmm<DHF / 4><<<spmm_blocks, 256>>>(h, pooled, eps, l);
            Ain = pooled; K1 = DHF;
            int o2 = (l - 1) * DHF * DHF, o1 = (l - 1) * DHF;
            wa = w1_r + o2; ba = b1_r + o1; ga = g1_r + o1; bea = be1_r + o1;
            wb = w2_r + o2; bb = b2_r + o1; gb = gbn_r + o1; bbb = bbn_r + o1;
        }

        // GEMM1: plain A
        k_gemm_tc<<<gemm_blocks, 512>>>(Ain, wa, ba, mid, NN, K1,
                                        nullptr, nullptr, nullptr, nullptr,
                                        sumb + (2 * l) * DHF, sumsqb + (2 * l) * DHF);
        // GEMM2: BN+ReLU on A computed in-kernel from slot-2l stats
        k_gemm_tc<<<gemm_blocks, 512>>>(mid, wb, bb, rep, NN, DHF,
                                        ga, bea, sumb + (2 * l) * DHF, sumsqb + (2 * l) * DHF,
                                        sumb + (2 * l + 1) * DHF, sumsqb + (2 * l + 1) * DHF);

        // fused BN + ReLU + pool, chunk-parallel; h written for layers 0..2
        k_bnpool<<<pool_blocks, DHF>>>(rep, h, out, DINF + l * DHF, gb, bbb,
                                       gid, 2 * l + 1, (l < NLAY - 1) ? 1 : 0);
    }

    // pooled x -> out[:, 0:200], chunk-parallel
    k_poolx<<<pool_blocks, 256>>>(x, out, gid);
}

// round 5
// speedup vs baseline: 1.4370x; 1.1421x over previous
#include <cuda_runtime.h>
#include <cuda_bf16.h>
#include <cstdint>

// Problem constants (fixed-shape problem)
#define NN      50000
#define EE_MAX  800000
#define GG      128
#define DINF    200
#define DHF     128
#define NLAY    4
#define BN_EPS  1e-5f
#define OUTW    (DINF + NLAY * DHF)   // 712
#define BNP_ROWS 128                  // rows per pooling chunk-block

// ---------------- scratch (device globals; no allocation allowed) ----------
__device__ float g_pooled0[NN * DINF];
__device__ float g_pooled [NN * DHF];
__device__ float g_mid    [NN * DHF];
__device__ float g_rep    [NN * DHF];
__device__ float g_h      [NN * DHF];
__device__ int   g_cnt    [2 * NN];      // [0,NN): hist, [NN,2NN): scatter cursor
__device__ int   g_rowptr [NN + 1];
__device__ int   g_colidx [EE_MAX];
__device__ float g_sum    [2 * NLAY][DHF];
__device__ float g_sumsq  [2 * NLAY][DHF];

// ---------------- CSR build ------------------------------------------------
__global__ void k_hist(const int* __restrict__ erow, int E) {
    int e = blockIdx.x * blockDim.x + threadIdx.x;
    if (e < E) atomicAdd(&g_cnt[erow[e]], 1);
}

// single-block scan, coalesced via big dynamic smem staging.
// Also zeroes the scatter cursors and the BN stat slots for this replay.
__global__ void k_scan_big() {
    extern __shared__ int sc[];            // [NN] + [1024] partials
    int* part = sc + NN;
    const int T = 1024;
    int t = threadIdx.x;

    if (t < DHF) {
        for (int l = 0; l < 2 * NLAY; l++) { g_sum[l][t] = 0.f; g_sumsq[l][t] = 0.f; }
    }
    for (int i = t; i < NN; i += T) {
        sc[i] = g_cnt[i];
        g_cnt[NN + i] = 0;
    }
    __syncthreads();

    const int C = (NN + T - 1) / T;
    int base = t * C;
    int s = 0;
    for (int j = 0; j < C; j++) {
        int i = base + j;
        if (i < NN) s += sc[i];
    }
    part[t] = s;
    __syncthreads();
    for (int off = 1; off < T; off <<= 1) {
        int v = (t >= off) ? part[t - off] : 0;
        __syncthreads();
        part[t] += v;
        __syncthreads();
    }
    int pre = (t > 0) ? part[t - 1] : 0;
    for (int j = 0; j < C; j++) {
        int i = base + j;
        if (i < NN) {
            int c = sc[i];
            sc[i] = pre;
            pre += c;
        }
    }
    __syncthreads();
    for (int i = t; i < NN; i += T) g_rowptr[i] = sc[i];
    if (t == T - 1) g_rowptr[NN] = pre;
}

__global__ void k_scatter(const int* __restrict__ erow, const int* __restrict__ ecol, int E) {
    int e = blockIdx.x * blockDim.x + threadIdx.x;
    if (e < E) {
        int r = erow[e];
        int p = g_rowptr[r] + atomicAdd(&g_cnt[NN + r], 1);
        g_colidx[p] = ecol[e];
    }
}

// ---------------- SpMM (pull / CSR, one warp per destination node) ---------
template <int D4>
__global__ void k_spmm(const float* __restrict__ hin, float* __restrict__ pout,
                       const float* __restrict__ epsv, int li) {
    int wid  = blockIdx.x * 8 + (threadIdx.x >> 5);
    int lane = threadIdx.x & 31;
    if (wid >= NN) return;
    const int S = (D4 + 31) / 32;
    float se = 1.0f + epsv[li];

    const float4* selfr = (const float4*)hin + (size_t)wid * D4;
    float4 acc[S];
#pragma unroll
    for (int s = 0; s < S; s++) {
        int j = lane + 32 * s;
        if (j < D4) {
            float4 v = selfr[j];
            acc[s] = make_float4(v.x * se, v.y * se, v.z * se, v.w * se);
        } else {
            acc[s] = make_float4(0.f, 0.f, 0.f, 0.f);
        }
    }
    int e0 = g_rowptr[wid], e1 = g_rowptr[wid + 1];
    int e = e0;
    for (; e + 2 <= e1; e += 2) {
        int c0 = g_colidx[e];
        int c1 = g_colidx[e + 1];
        const float4* r0 = (const float4*)hin + (size_t)c0 * D4;
        const float4* r1 = (const float4*)hin + (size_t)c1 * D4;
#pragma unroll
        for (int s = 0; s < S; s++) {
            int j = lane + 32 * s;
            if (j < D4) {
                float4 v0 = r0[j];
                float4 v1 = r1[j];
                acc[s].x += v0.x + v1.x;
                acc[s].y += v0.y + v1.y;
                acc[s].z += v0.z + v1.z;
                acc[s].w += v0.w + v1.w;
            }
        }
    }
    if (e < e1) {
        int c = g_colidx[e];
        const float4* r = (const float4*)hin + (size_t)c * D4;
#pragma unroll
        for (int s = 0; s < S; s++) {
            int j = lane + 32 * s;
            if (j < D4) {
                float4 v = r[j];
                acc[s].x += v.x; acc[s].y += v.y; acc[s].z += v.z; acc[s].w += v.w;
            }
        }
    }
    float4* o = (float4*)pout + (size_t)wid * D4;
#pragma unroll
    for (int s = 0; s < S; s++) {
        int j = lane + 32 * s;
        if (j < D4) o[j] = acc[s];
    }
}

// ---------------- 3xBF16 tensor-core GEMM ----------------------------------
// C[M,128] = f(A[M,K]) @ W[K,128] + bias via hi/lo bf16 split:
//   v = hi + lo, products hi*hi + lo*hi + hi*lo  (residual ~2^-18)
// mma.m16n8k16.bf16: one mma covers a full BK=16 k-slice.

__device__ __forceinline__ uint32_t pack_bf16(float v0, float v1, float& rem0, float& rem1) {
    __nv_bfloat16 h0 = __float2bfloat16(v0);
    __nv_bfloat16 h1 = __float2bfloat16(v1);
    rem0 = v0 - __bfloat162float(h0);
    rem1 = v1 - __bfloat162float(h1);
    return ((uint32_t)__bfloat16_as_ushort(h1) << 16) | (uint32_t)__bfloat16_as_ushort(h0);
}

__device__ __forceinline__ uint32_t pack_bf16_rn(float v0, float v1) {
    __nv_bfloat162 p = __floats2bfloat162_rn(v0, v1);   // .x = v0 (low half)
    return *(uint32_t*)&p;
}

__device__ __forceinline__ void mma16(float* c, const uint32_t* a, const uint32_t* b) {
    asm volatile(
        "mma.sync.aligned.m16n8k16.row.col.f32.bf16.bf16.f32 "
        "{%0,%1,%2,%3}, {%4,%5,%6,%7}, {%8,%9}, {%0,%1,%2,%3};"
        : "+f"(c[0]), "+f"(c[1]), "+f"(c[2]), "+f"(c[3])
        : "r"(a[0]), "r"(a[1]), "r"(a[2]), "r"(a[3]), "r"(b[0]), "r"(b[1]));
}

__global__ __launch_bounds__(512, 2)
void k_gemm_tc(const float* __restrict__ A, const float* __restrict__ W,
               const float* __restrict__ bias, float* __restrict__ C,
               int M, int K,
               const float* __restrict__ bnga, const float* __restrict__ bnbe,
               const float* __restrict__ psum, const float* __restrict__ psq,
               float* __restrict__ osum, float* __restrict__ osumsq) {
    // packed bf16x2 words: [k/2][row-or-col]; pad 136 -> LDS bank permutation
    __shared__ uint32_t ash[8][136], asl[8][136];
    __shared__ uint32_t wsh[8][136], wsl[8][136];
    __shared__ float strs[DHF], strh[DHF];

    const int tid  = threadIdx.x;
    const int lane = tid & 31;
    const int wid  = tid >> 5;
    const int wr   = wid >> 2;
    const int wc   = wid & 3;
    const int gid  = lane >> 2;
    const int tq   = lane & 3;
    const int row0 = blockIdx.x * 128;

    const int ar = tid & 127;    // A row within tile / W column
    const int kg = tid >> 7;     // 0..3 -> k = 4*kg + j

    const bool use_bn = (bnga != nullptr);
    if (use_bn) {
        if (tid < DHF) {
            const float invN = 1.0f / NN;
            float m = psum[tid] * invN;
            float v = psq[tid] * invN - m * m;
            float rs = rsqrtf(v + BN_EPS);
            float sc = bnga[tid] * rs;
            strs[tid] = sc;
            strh[tid] = bnbe[tid] - m * sc;
        }
        __syncthreads();
    }

    float acc[2][4][4];
#pragma unroll
    for (int mt = 0; mt < 2; mt++)
#pragma unroll
        for (int nt = 0; nt < 4; nt++)
#pragma unroll
            for (int j = 0; j < 4; j++) acc[mt][nt][j] = 0.f;

    const int T = (K + 15) >> 4;
    const int gr = row0 + ar;
    const bool rok = (gr < M);

    float4 va;
    float wv[4];

    {
        int gk0 = 4 * kg;
        va = make_float4(0.f, 0.f, 0.f, 0.f);
        if (rok && gk0 < K) va = *(const float4*)&A[(size_t)gr * K + gk0];
#pragma unroll
        for (int j = 0; j < 4; j++) {
            int kw = 4 * kg + j;
            wv[j] = (kw < K) ? W[(size_t)kw * 128 + ar] : 0.f;
        }
    }

    for (int t = 0; t < T; t++) {
        int k0 = t * 16;
        // ---- stage current tile (hi/lo bf16 split, packed pairs) ----
        {
            float a4[4] = {va.x, va.y, va.z, va.w};
            if (use_bn && rok) {
#pragma unroll
                for (int j = 0; j < 4; j++) {
                    int gk = k0 + 4 * kg + j;
                    a4[j] = (gk < K) ? fmaxf(a4[j] * strs[gk] + strh[gk], 0.f) : 0.f;
                }
            }
#pragma unroll
            for (int p = 0; p < 2; p++) {
                float r0f, r1f;
                ash[2 * kg + p][ar] = pack_bf16(a4[2 * p], a4[2 * p + 1], r0f, r1f);
                asl[2 * kg + p][ar] = pack_bf16_rn(r0f, r1f);
                float s0, s1;
                wsh[2 * kg + p][ar] = pack_bf16(wv[2 * p], wv[2 * p + 1], s0, s1);
                wsl[2 * kg + p][ar] = pack_bf16_rn(s0, s1);
            }
        }
        __syncthreads();

        // ---- prefetch next tile ----
        if (t + 1 < T) {
            int kb = (t + 1) * 16;
            int gk0 = kb + 4 * kg;
            va = make_float4(0.f, 0.f, 0.f, 0.f);
            if (rok && gk0 < K) va = *(const float4*)&A[(size_t)gr * K + gk0];
#pragma unroll
            for (int j = 0; j < 4; j++) {
                int kw = kb + 4 * kg + j;
                wv[j] = (kw < K) ? W[(size_t)kw * 128 + ar] : 0.f;
            }
        }

        // ---- mma over the resident tile (one k16 step) ----
        {
            uint32_t bh[4][2], bl[4][2];
#pragma unroll
            for (int nt = 0; nt < 4; nt++) {
                int col = wc * 32 + nt * 8 + gid;
                bh[nt][0] = wsh[tq][col];
                bh[nt][1] = wsh[tq + 4][col];
                bl[nt][0] = wsl[tq][col];
                bl[nt][1] = wsl[tq + 4][col];
            }
#pragma unroll
            for (int mt = 0; mt < 2; mt++) {
                int r0 = wr * 32 + mt * 16;
                uint32_t ah[4], al[4];
                ah[0] = ash[tq][r0 + gid];
                ah[1] = ash[tq][r0 + gid + 8];
                ah[2] = ash[tq + 4][r0 + gid];
                ah[3] = ash[tq + 4][r0 + gid + 8];
                al[0] = asl[tq][r0 + gid];
                al[1] = asl[tq][r0 + gid + 8];
                al[2] = asl[tq + 4][r0 + gid];
                al[3] = asl[tq + 4][r0 + gid + 8];
#pragma unroll
                for (int nt = 0; nt < 4; nt++) {
                    mma16(acc[mt][nt], ah, bh[nt]);   // hi*hi
                    mma16(acc[mt][nt], al, bh[nt]);   // lo*hi
                    mma16(acc[mt][nt], ah, bl[nt]);   // hi*lo
                }
            }
        }
        __syncthreads();
    }

    // ---- epilogue: bias, store, column stats ----
    float cs[4][2], cq[4][2];
#pragma unroll
    for (int nt = 0; nt < 4; nt++)
#pragma unroll
        for (int j = 0; j < 2; j++) { cs[nt][j] = 0.f; cq[nt][j] = 0.f; }

#pragma unroll
    for (int mt = 0; mt < 2; mt++) {
        int rbase = row0 + wr * 32 + mt * 16;
#pragma unroll
        for (int nt = 0; nt < 4; nt++) {
            int colb = wc * 32 + nt * 8 + 2 * tq;
            float b0 = bias[colb], b1 = bias[colb + 1];
            int r1 = rbase + gid;
            int r2 = rbase + gid + 8;
            if (r1 < M) {
                float v0 = acc[mt][nt][0] + b0;
                float v1 = acc[mt][nt][1] + b1;
                *(float2*)&C[(size_t)r1 * 128 + colb] = make_float2(v0, v1);
                cs[nt][0] += v0; cq[nt][0] += v0 * v0;
                cs[nt][1] += v1; cq[nt][1] += v1 * v1;
            }
            if (r2 < M) {
                float v0 = acc[mt][nt][2] + b0;
                float v1 = acc[mt][nt][3] + b1;
                *(float2*)&C[(size_t)r2 * 128 + colb] = make_float2(v0, v1);
                cs[nt][0] += v0; cq[nt][0] += v0 * v0;
                cs[nt][1] += v1; cq[nt][1] += v1 * v1;
            }
        }
    }
#pragma unroll
    for (int nt = 0; nt < 4; nt++)
#pragma unroll
        for (int j = 0; j < 2; j++) {
            float s = cs[nt][j], q = cq[nt][j];
            s += __shfl_xor_sync(0xffffffffu, s, 4);
            s += __shfl_xor_sync(0xffffffffu, s, 8);
            s += __shfl_xor_sync(0xffffffffu, s, 16);
            q += __shfl_xor_sync(0xffffffffu, q, 4);
            q += __shfl_xor_sync(0xffffffffu, q, 8);
            q += __shfl_xor_sync(0xffffffffu, q, 16);
            if (gid == 0) {
                int col = wc * 32 + nt * 8 + 2 * tq + j;
                atomicAdd(&osum[col], s);
                atomicAdd(&osumsq[col], q);
            }
        }
}

// ------ fused BN + ReLU + graph pool, CHUNK-PARALLEL (block = 128 rows) ----
__global__ void k_bnpool(const float* __restrict__ rep, float* __restrict__ h,
                         float* __restrict__ out, int off,
                         const float* __restrict__ gamma, const float* __restrict__ beta,
                         const int* __restrict__ gids, int slot, int write_h) {
    int c = threadIdx.x;                  // 128 threads = columns
    int r0 = blockIdx.x * BNP_ROWS;
    int r1 = min(r0 + BNP_ROWS, NN);
    const float invN = 1.0f / NN;
    float m = g_sum[slot][c] * invN;
    float v = g_sumsq[slot][c] * invN - m * m;
    float sc = gamma[c] * rsqrtf(v + BN_EPS);
    float sh = beta[c] - m * sc;

    int curg = gids[r0];
    float acc = 0.f;
    for (int r = r0; r < r1; r++) {
        int gr = gids[r];
        if (gr != curg) {
            atomicAdd(&out[(size_t)curg * OUTW + off + c], acc);
            acc = 0.f;
            curg = gr;
        }
        float xv = fmaxf(rep[(size_t)r * DHF + c] * sc + sh, 0.f);
        if (write_h) h[(size_t)r * DHF + c] = xv;
        acc += xv;
    }
    atomicAdd(&out[(size_t)curg * OUTW + off + c], acc);
}

// chunk-parallel pooling of raw x (D=200) into out[:, 0:200]
__global__ void k_poolx(const float* __restrict__ src, float* __restrict__ out,
                        const int* __restrict__ gids) {
    int c = threadIdx.x;                  // 256 threads, guard to 200
    if (c >= DINF) return;
    int r0 = blockIdx.x * BNP_ROWS;
    int r1 = min(r0 + BNP_ROWS, NN);
    int curg = gids[r0];
    float acc = 0.f;
    for (int r = r0; r < r1; r++) {
        int gr = gids[r];
        if (gr != curg) {
            atomicAdd(&out[(size_t)curg * OUTW + c], acc);
            acc = 0.f;
            curg = gr;
        }
        acc += src[(size_t)r * DINF + c];
    }
    atomicAdd(&out[(size_t)curg * OUTW + c], acc);
}

// ---------------- launch ---------------------------------------------------
extern "C" void kernel_launch(void* const* d_in, const int* in_sizes, int n_in,
                              void* d_out, int out_size) {
    const float* x     = (const float*)d_in[0];
    const int*   erow  = (const int*)d_in[1];
    const int*   ecol  = (const int*)d_in[2];
    const int*   gid   = (const int*)d_in[3];
    const float* eps   = (const float*)d_in[4];
    const float* w1_0  = (const float*)d_in[5];
    const float* b1_0  = (const float*)d_in[6];
    const float* g1_0  = (const float*)d_in[7];
    const float* be1_0 = (const float*)d_in[8];
    const float* w2_0  = (const float*)d_in[9];
    const float* b2_0  = (const float*)d_in[10];
    const float* gbn_0 = (const float*)d_in[11];
    const float* bbn_0 = (const float*)d_in[12];
    const float* w1_r  = (const float*)d_in[13];
    const float* b1_r  = (const float*)d_in[14];
    const float* g1_r  = (const float*)d_in[15];
    const float* be1_r = (const float*)d_in[16];
    const float* w2_r  = (const float*)d_in[17];
    const float* b2_r  = (const float*)d_in[18];
    const float* gbn_r = (const float*)d_in[19];
    const float* bbn_r = (const float*)d_in[20];
    float* out = (float*)d_out;

    int E = in_sizes[1];

    float *pooled0, *pooled, *mid, *rep, *h, *sumb, *sumsqb;
    int *cnt;
    cudaGetSymbolAddress((void**)&pooled0, g_pooled0);
    cudaGetSymbolAddress((void**)&pooled,  g_pooled);
    cudaGetSymbolAddress((void**)&mid,     g_mid);
    cudaGetSymbolAddress((void**)&rep,     g_rep);
    cudaGetSymbolAddress((void**)&h,       g_h);
    cudaGetSymbolAddress((void**)&sumb,    g_sum);
    cudaGetSymbolAddress((void**)&sumsqb,  g_sumsq);
    cudaGetSymbolAddress((void**)&cnt,     g_cnt);

    const int scan_smem = (NN + 1024) * (int)sizeof(int);
    cudaFuncSetAttribute(k_scan_big, cudaFuncAttributeMaxDynamicSharedMemorySize, scan_smem);

    // ---- CSR build + output zeroing ----
    cudaMemsetAsync(cnt, 0, NN * sizeof(int));
    cudaMemsetAsync(out, 0, (size_t)out_size * sizeof(float));
    k_hist<<<(E + 255) / 256, 256>>>(erow, E);
    k_scan_big<<<1, 1024, scan_smem>>>();          // + zero cursors & BN stats
    k_scatter<<<(E + 255) / 256, 256>>>(erow, ecol, E);

    const int spmm_blocks = (NN + 7) / 8;
    const int gemm_blocks = (NN + 127) / 128;
    const int pool_blocks = (NN + BNP_ROWS - 1) / BNP_ROWS;

    for (int l = 0; l < NLAY; l++) {
        const float *wa, *ba, *ga, *bea, *wb, *bb, *gb, *bbb;
        const float* Ain;
        int K1;
        if (l == 0) {
            k_spmm<DINF / 4><<<spmm_blocks, 256>>>(x, pooled0, eps, 0);
            Ain = pooled0; K1 = DINF;
            wa = w1_0; ba = b1_0; ga = g1_0; bea = be1_0;
            wb = w2_0; bb = b2_0; gb = gbn_0; bbb = bbn_0;
        } else {
            k_spmm<DHF / 4><<<spmm_blocks, 256>>>(h, pooled, eps, l);
            Ain = pooled; K1 = DHF;
            int o2 = (l - 1) * DHF * DHF, o1 = (l - 1) * DHF;
            wa = w1_r + o2; ba = b1_r + o1; ga = g1_r + o1; bea = be1_r + o1;
            wb = w2_r + o2; bb = b2_r + o1; gb = gbn_r + o1; bbb = bbn_r + o1;
        }

        // GEMM1: plain A
        k_gemm_tc<<<gemm_blocks, 512>>>(Ain, wa, ba, mid, NN, K1,
                                        nullptr, nullptr, nullptr, nullptr,
                                        sumb + (2 * l) * DHF, sumsqb + (2 * l) * DHF);
        // GEMM2: BN+ReLU on A computed in-kernel from slot-2l stats
        k_gemm_tc<<<gemm_blocks, 512>>>(mid, wb, bb, rep, NN, DHF,
                                        ga, bea, sumb + (2 * l) * DHF, sumsqb + (2 * l) * DHF,
                                        sumb + (2 * l + 1) * DHF, sumsqb + (2 * l + 1) * DHF);

        // fused BN + ReLU + pool, chunk-parallel; h written for layers 0..2
        k_bnpool<<<pool_blocks, DHF>>>(rep, h, out, DINF + l * DHF, gb, bbb,
                                       gid, 2 * l + 1, (l < NLAY - 1) ? 1 : 0);
    }

    // pooled x -> out[:, 0:200], chunk-parallel
    k_poolx<<<pool_blocks, 256>>>(x, out, gid);
}

// round 6
// speedup vs baseline: 1.5446x; 1.0749x over previous
#include <cuda_runtime.h>
#include <cuda_bf16.h>
#include <cstdint>

// Problem constants (fixed-shape problem)
#define NN      50000
#define EE_MAX  800000
#define GG      128
#define DINF    200
#define DHF     128
#define NLAY    4
#define BN_EPS  1e-5f
#define OUTW    (DINF + NLAY * DHF)   // 712
#define BNP_ROWS 128                  // rows per pooling chunk-block
#define WPAIRS  548                   // total bf16-pair rows across all 8 weights

// ---------------- scratch (device globals; no allocation allowed) ----------
__device__ float g_pooled0[NN * DINF];
__device__ float g_pooled [NN * DHF];
__device__ float g_mid    [NN * DHF];
__device__ float g_rep    [NN * DHF];
__device__ float g_h      [NN * DHF];
__device__ int   g_cnt    [2 * NN];      // [0,NN): hist, [NN,2NN): scatter cursor
__device__ int   g_rowptr [NN + 1];
__device__ int   g_colidx [EE_MAX];
__device__ float g_sum    [2 * NLAY][DHF];
__device__ float g_sumsq  [2 * NLAY][DHF];
__device__ uint2 g_wpk    [WPAIRS * DHF];   // .x = hi bf16x2, .y = lo bf16x2

// ---------------- bf16 hi/lo split helpers ---------------------------------
__device__ __forceinline__ uint32_t pack_bf16(float v0, float v1, float& rem0, float& rem1) {
    __nv_bfloat16 h0 = __float2bfloat16(v0);
    __nv_bfloat16 h1 = __float2bfloat16(v1);
    rem0 = v0 - __bfloat162float(h0);
    rem1 = v1 - __bfloat162float(h1);
    return ((uint32_t)__bfloat16_as_ushort(h1) << 16) | (uint32_t)__bfloat16_as_ushort(h0);
}

__device__ __forceinline__ uint32_t pack_bf16_rn(float v0, float v1) {
    __nv_bfloat162 p = __floats2bfloat162_rn(v0, v1);   // .x = v0 (low half)
    return *(uint32_t*)&p;
}

// ---------------- CSR build ------------------------------------------------
__global__ void k_hist(const int* __restrict__ erow, int E) {
    int e = blockIdx.x * blockDim.x + threadIdx.x;
    if (e < E) atomicAdd(&g_cnt[erow[e]], 1);
}

// single-block scan, coalesced via big dynamic smem staging.
// Also zeroes the scatter cursors and the BN stat slots for this replay.
__global__ void k_scan_big() {
    extern __shared__ int sc[];            // [NN] + [1024] partials
    int* part = sc + NN;
    const int T = 1024;
    int t = threadIdx.x;

    if (t < DHF) {
        for (int l = 0; l < 2 * NLAY; l++) { g_sum[l][t] = 0.f; g_sumsq[l][t] = 0.f; }
    }
    for (int i = t; i < NN; i += T) {
        sc[i] = g_cnt[i];
        g_cnt[NN + i] = 0;
    }
    __syncthreads();

    const int C = (NN + T - 1) / T;
    int base = t * C;
    int s = 0;
    for (int j = 0; j < C; j++) {
        int i = base + j;
        if (i < NN) s += sc[i];
    }
    part[t] = s;
    __syncthreads();
    for (int off = 1; off < T; off <<= 1) {
        int v = (t >= off) ? part[t - off] : 0;
        __syncthreads();
        part[t] += v;
        __syncthreads();
    }
    int pre = (t > 0) ? part[t - 1] : 0;
    for (int j = 0; j < C; j++) {
        int i = base + j;
        if (i < NN) {
            int c = sc[i];
            sc[i] = pre;
            pre += c;
        }
    }
    __syncthreads();
    for (int i = t; i < NN; i += T) g_rowptr[i] = sc[i];
    if (t == T - 1) g_rowptr[NN] = pre;
}

__global__ void k_scatter(const int* __restrict__ erow, const int* __restrict__ ecol, int E) {
    int e = blockIdx.x * blockDim.x + threadIdx.x;
    if (e < E) {
        int r = erow[e];
        int p = g_rowptr[r] + atomicAdd(&g_cnt[NN + r], 1);
        g_colidx[p] = ecol[e];
    }
}

// ---- split all 8 weight matrices into packed bf16 hi/lo (once per replay) --
// segment layout in g_wpk (pair-rows):
//  [0,100)   w1_0 (K=200)        [100,164) w2_0
//  [164,228) w1_r[0]  [228,292) w1_r[1]  [292,356) w1_r[2]
//  [356,420) w2_r[0]  [420,484) w2_r[1]  [484,548) w2_r[2]
__global__ void k_splitw(const float* __restrict__ w1_0, const float* __restrict__ w2_0,
                         const float* __restrict__ w1_r, const float* __restrict__ w2_r) {
    int b = blockIdx.x;        // pair-row 0..547
    int c = threadIdx.x;       // column 0..127
    const float* src;
    int kp;
    if (b < 100)      { src = w1_0; kp = b; }
    else if (b < 164) { src = w2_0; kp = b - 100; }
    else {
        int r = b - 164;
        if (r < 192) { src = w1_r + (r / 64) * DHF * DHF; kp = r % 64; }
        else { r -= 192; src = w2_r + (r / 64) * DHF * DHF; kp = r % 64; }
    }
    float v0 = src[(size_t)(2 * kp) * DHF + c];
    float v1 = src[(size_t)(2 * kp + 1) * DHF + c];
    float r0, r1;
    uint32_t hi = pack_bf16(v0, v1, r0, r1);
    uint32_t lo = pack_bf16_rn(r0, r1);
    g_wpk[b * DHF + c] = make_uint2(hi, lo);
}

// ---------------- SpMM (pull / CSR, one warp per destination node) ---------
template <int D4>
__global__ void k_spmm(const float* __restrict__ hin, float* __restrict__ pout,
                       const float* __restrict__ epsv, int li) {
    int wid  = blockIdx.x * 8 + (threadIdx.x >> 5);
    int lane = threadIdx.x & 31;
    if (wid >= NN) return;
    const int S = (D4 + 31) / 32;
    float se = 1.0f + epsv[li];

    const float4* selfr = (const float4*)hin + (size_t)wid * D4;
    float4 acc[S];
#pragma unroll
    for (int s = 0; s < S; s++) {
        int j = lane + 32 * s;
        if (j < D4) {
            float4 v = selfr[j];
            acc[s] = make_float4(v.x * se, v.y * se, v.z * se, v.w * se);
        } else {
            acc[s] = make_float4(0.f, 0.f, 0.f, 0.f);
        }
    }
    int e0 = g_rowptr[wid], e1 = g_rowptr[wid + 1];
    int e = e0;
    for (; e + 2 <= e1; e += 2) {
        int c0 = g_colidx[e];
        int c1 = g_colidx[e + 1];
        const float4* r0 = (const float4*)hin + (size_t)c0 * D4;
        const float4* r1 = (const float4*)hin + (size_t)c1 * D4;
#pragma unroll
        for (int s = 0; s < S; s++) {
            int j = lane + 32 * s;
            if (j < D4) {
                float4 v0 = r0[j];
                float4 v1 = r1[j];
                acc[s].x += v0.x + v1.x;
                acc[s].y += v0.y + v1.y;
                acc[s].z += v0.z + v1.z;
                acc[s].w += v0.w + v1.w;
            }
        }
    }
    if (e < e1) {
        int c = g_colidx[e];
        const float4* r = (const float4*)hin + (size_t)c * D4;
#pragma unroll
        for (int s = 0; s < S; s++) {
            int j = lane + 32 * s;
            if (j < D4) {
                float4 v = r[j];
                acc[s].x += v.x; acc[s].y += v.y; acc[s].z += v.z; acc[s].w += v.w;
            }
        }
    }
    float4* o = (float4*)pout + (size_t)wid * D4;
#pragma unroll
    for (int s = 0; s < S; s++) {
        int j = lane + 32 * s;
        if (j < D4) o[j] = acc[s];
    }
}

// ---------------- 3xBF16 tensor-core GEMM (double-buffered) ----------------
__device__ __forceinline__ void mma16(float* c, const uint32_t* a, const uint32_t* b) {
    asm volatile(
        "mma.sync.aligned.m16n8k16.row.col.f32.bf16.bf16.f32 "
        "{%0,%1,%2,%3}, {%4,%5,%6,%7}, {%8,%9}, {%0,%1,%2,%3};"
        : "+f"(c[0]), "+f"(c[1]), "+f"(c[2]), "+f"(c[3])
        : "r"(a[0]), "r"(a[1]), "r"(a[2]), "r"(a[3]), "r"(b[0]), "r"(b[1]));
}

__global__ __launch_bounds__(512, 2)
void k_gemm_tc(const float* __restrict__ A, const uint2* __restrict__ wpk,
               const float* __restrict__ bias, float* __restrict__ C,
               int M, int K,
               const float* __restrict__ bnga, const float* __restrict__ bnbe,
               const float* __restrict__ psum, const float* __restrict__ psq,
               float* __restrict__ osum, float* __restrict__ osumsq) {
    // double-buffered packed bf16x2 tiles; pad 136 -> LDS bank permutation
    __shared__ uint32_t ash[2][8][136], asl[2][8][136];
    __shared__ uint32_t wsh[2][8][136], wsl[2][8][136];
    __shared__ float strs[DHF], strh[DHF];

    const int tid  = threadIdx.x;
    const int lane = tid & 31;
    const int wid  = tid >> 5;
    const int wr   = wid >> 2;
    const int wc   = wid & 3;
    const int gid  = lane >> 2;
    const int tq   = lane & 3;
    const int row0 = blockIdx.x * 128;

    const int ar = tid & 127;    // A row within tile / W column
    const int kg = tid >> 7;     // 0..3

    const int KP = K >> 1;       // weight pair-rows

    const bool use_bn = (bnga != nullptr);
    if (use_bn) {
        if (tid < DHF) {
            const float invN = 1.0f / NN;
            float m = psum[tid] * invN;
            float v = psq[tid] * invN - m * m;
            float rs = rsqrtf(v + BN_EPS);
            float sc = bnga[tid] * rs;
            strs[tid] = sc;
            strh[tid] = bnbe[tid] - m * sc;
        }
        __syncthreads();
    }

    float acc[2][4][4];
#pragma unroll
    for (int mt = 0; mt < 2; mt++)
#pragma unroll
        for (int nt = 0; nt < 4; nt++)
#pragma unroll
            for (int j = 0; j < 4; j++) acc[mt][nt][j] = 0.f;

    const int T = (K + 15) >> 4;
    const int gr = row0 + ar;
    const bool rok = (gr < M);

    float4 va;
    uint2 wk0, wk1;

    auto prefetch = [&](int t) {
        int gk0 = t * 16 + 4 * kg;
        va = make_float4(0.f, 0.f, 0.f, 0.f);
        if (rok && gk0 < K) va = *(const float4*)&A[(size_t)gr * K + gk0];
        int kp0 = t * 8 + 2 * kg;
        wk0 = (kp0 < KP)     ? wpk[kp0 * DHF + ar]       : make_uint2(0u, 0u);
        wk1 = (kp0 + 1 < KP) ? wpk[(kp0 + 1) * DHF + ar] : make_uint2(0u, 0u);
    };

    auto stage = [&](int d, int k0) {
        float a4[4] = {va.x, va.y, va.z, va.w};
        if (use_bn && rok) {
#pragma unroll
            for (int j = 0; j < 4; j++) {
                int gk = k0 + 4 * kg + j;
                a4[j] = (gk < K) ? fmaxf(a4[j] * strs[gk] + strh[gk], 0.f) : 0.f;
            }
        }
#pragma unroll
        for (int p = 0; p < 2; p++) {
            float r0f, r1f;
            ash[d][2 * kg + p][ar] = pack_bf16(a4[2 * p], a4[2 * p + 1], r0f, r1f);
            asl[d][2 * kg + p][ar] = pack_bf16_rn(r0f, r1f);
        }
        wsh[d][2 * kg][ar]     = wk0.x;
        wsl[d][2 * kg][ar]     = wk0.y;
        wsh[d][2 * kg + 1][ar] = wk1.x;
        wsl[d][2 * kg + 1][ar] = wk1.y;
    };

    prefetch(0);
    stage(0, 0);
    __syncthreads();

    for (int t = 0; t < T; t++) {
        const int cur = t & 1;
        if (t + 1 < T) prefetch(t + 1);

        // ---- mma over resident tile (one k16 step, 3-term split) ----
        {
            uint32_t bh[4][2], bl[4][2];
#pragma unroll
            for (int nt = 0; nt < 4; nt++) {
                int col = wc * 32 + nt * 8 + gid;
                bh[nt][0] = wsh[cur][tq][col];
                bh[nt][1] = wsh[cur][tq + 4][col];
                bl[nt][0] = wsl[cur][tq][col];
                bl[nt][1] = wsl[cur][tq + 4][col];
            }
#pragma unroll
            for (int mt = 0; mt < 2; mt++) {
                int r0 = wr * 32 + mt * 16;
                uint32_t ah[4], al[4];
                ah[0] = ash[cur][tq][r0 + gid];
                ah[1] = ash[cur][tq][r0 + gid + 8];
                ah[2] = ash[cur][tq + 4][r0 + gid];
                ah[3] = ash[cur][tq + 4][r0 + gid + 8];
                al[0] = asl[cur][tq][r0 + gid];
                al[1] = asl[cur][tq][r0 + gid + 8];
                al[2] = asl[cur][tq + 4][r0 + gid];
                al[3] = asl[cur][tq + 4][r0 + gid + 8];
#pragma unroll
                for (int nt = 0; nt < 4; nt++) {
                    mma16(acc[mt][nt], ah, bh[nt]);   // hi*hi
                    mma16(acc[mt][nt], al, bh[nt]);   // lo*hi
                    mma16(acc[mt][nt], ah, bl[nt]);   // hi*lo
                }
            }
        }

        if (t + 1 < T) stage((t + 1) & 1, (t + 1) * 16);
        __syncthreads();
    }

    // ---- epilogue: bias, store, column stats ----
    float cs[4][2], cq[4][2];
#pragma unroll
    for (int nt = 0; nt < 4; nt++)
#pragma unroll
        for (int j = 0; j < 2; j++) { cs[nt][j] = 0.f; cq[nt][j] = 0.f; }

#pragma unroll
    for (int mt = 0; mt < 2; mt++) {
        int rbase = row0 + wr * 32 + mt * 16;
#pragma unroll
        for (int nt = 0; nt < 4; nt++) {
            int colb = wc * 32 + nt * 8 + 2 * tq;
            float b0 = bias[colb], b1 = bias[colb + 1];
            int r1 = rbase + gid;
            int r2 = rbase + gid + 8;
            if (r1 < M) {
                float v0 = acc[mt][nt][0] + b0;
                float v1 = acc[mt][nt][1] + b1;
                *(float2*)&C[(size_t)r1 * 128 + colb] = make_float2(v0, v1);
                cs[nt][0] += v0; cq[nt][0] += v0 * v0;
                cs[nt][1] += v1; cq[nt][1] += v1 * v1;
            }
            if (r2 < M) {
                float v0 = acc[mt][nt][2] + b0;
                float v1 = acc[mt][nt][3] + b1;
                *(float2*)&C[(size_t)r2 * 128 + colb] = make_float2(v0, v1);
                cs[nt][0] += v0; cq[nt][0] += v0 * v0;
                cs[nt][1] += v1; cq[nt][1] += v1 * v1;
            }
        }
    }
#pragma unroll
    for (int nt = 0; nt < 4; nt++)
#pragma unroll
        for (int j = 0; j < 2; j++) {
            float s = cs[nt][j], q = cq[nt][j];
            s += __shfl_xor_sync(0xffffffffu, s, 4);
            s += __shfl_xor_sync(0xffffffffu, s, 8);
            s += __shfl_xor_sync(0xffffffffu, s, 16);
            q += __shfl_xor_sync(0xffffffffu, q, 4);
            q += __shfl_xor_sync(0xffffffffu, q, 8);
            q += __shfl_xor_sync(0xffffffffu, q, 16);
            if (gid == 0) {
                int col = wc * 32 + nt * 8 + 2 * tq + j;
                atomicAdd(&osum[col], s);
                atomicAdd(&osumsq[col], q);
            }
        }
}

// ------ fused BN + ReLU + graph pool, CHUNK-PARALLEL (block = 128 rows) ----
__global__ void k_bnpool(const float* __restrict__ rep, float* __restrict__ h,
                         float* __restrict__ out, int off,
                         const float* __restrict__ gamma, const float* __restrict__ beta,
                         const int* __restrict__ gids, int slot, int write_h) {
    int c = threadIdx.x;                  // 128 threads = columns
    int r0 = blockIdx.x * BNP_ROWS;
    int r1 = min(r0 + BNP_ROWS, NN);
    const float invN = 1.0f / NN;
    float m = g_sum[slot][c] * invN;
    float v = g_sumsq[slot][c] * invN - m * m;
    float sc = gamma[c] * rsqrtf(v + BN_EPS);
    float sh = beta[c] - m * sc;

    int curg = gids[r0];
    float acc = 0.f;
    for (int r = r0; r < r1; r++) {
        int gr = gids[r];
        if (gr != curg) {
            atomicAdd(&out[(size_t)curg * OUTW + off + c], acc);
            acc = 0.f;
            curg = gr;
        }
        float xv = fmaxf(rep[(size_t)r * DHF + c] * sc + sh, 0.f);
        if (write_h) h[(size_t)r * DHF + c] = xv;
        acc += xv;
    }
    atomicAdd(&out[(size_t)curg * OUTW + off + c], acc);
}

// chunk-parallel pooling of raw x (D=200) into out[:, 0:200]
__global__ void k_poolx(const float* __restrict__ src, float* __restrict__ out,
                        const int* __restrict__ gids) {
    int c = threadIdx.x;                  // 256 threads, guard to 200
    if (c >= DINF) return;
    int r0 = blockIdx.x * BNP_ROWS;
    int r1 = min(r0 + BNP_ROWS, NN);
    int curg = gids[r0];
    float acc = 0.f;
    for (int r = r0; r < r1; r++) {
        int gr = gids[r];
        if (gr != curg) {
            atomicAdd(&out[(size_t)curg * OUTW + c], acc);
            acc = 0.f;
            curg = gr;
        }
        acc += src[(size_t)r * DINF + c];
    }
    atomicAdd(&out[(size_t)curg * OUTW + c], acc);
}

// ---------------- launch ---------------------------------------------------
extern "C" void kernel_launch(void* const* d_in, const int* in_sizes, int n_in,
                              void* d_out, int out_size) {
    const float* x     = (const float*)d_in[0];
    const int*   erow  = (const int*)d_in[1];
    const int*   ecol  = (const int*)d_in[2];
    const int*   gid   = (const int*)d_in[3];
    const float* eps   = (const float*)d_in[4];
    const float* w1_0  = (const float*)d_in[5];
    const float* b1_0  = (const float*)d_in[6];
    const float* g1_0  = (const float*)d_in[7];
    const float* be1_0 = (const float*)d_in[8];
    const float* w2_0  = (const float*)d_in[9];
    const float* b2_0  = (const float*)d_in[10];
    const float* gbn_0 = (const float*)d_in[11];
    const float* bbn_0 = (const float*)d_in[12];
    const float* w1_r  = (const float*)d_in[13];
    const float* b1_r  = (const float*)d_in[14];
    const float* g1_r  = (const float*)d_in[15];
    const float* be1_r = (const float*)d_in[16];
    const float* w2_r  = (const float*)d_in[17];
    const float* b2_r  = (const float*)d_in[18];
    const float* gbn_r = (const float*)d_in[19];
    const float* bbn_r = (const float*)d_in[20];
    float* out = (float*)d_out;

    int E = in_sizes[1];

    float *pooled0, *pooled, *mid, *rep, *h, *sumb, *sumsqb;
    int *cnt;
    uint2 *wpk;
    cudaGetSymbolAddress((void**)&pooled0, g_pooled0);
    cudaGetSymbolAddress((void**)&pooled,  g_pooled);
    cudaGetSymbolAddress((void**)&mid,     g_mid);
    cudaGetSymbolAddress((void**)&rep,     g_rep);
    cudaGetSymbolAddress((void**)&h,       g_h);
    cudaGetSymbolAddress((void**)&sumb,    g_sum);
    cudaGetSymbolAddress((void**)&sumsqb,  g_sumsq);
    cudaGetSymbolAddress((void**)&cnt,     g_cnt);
    cudaGetSymbolAddress((void**)&wpk,     g_wpk);

    const int scan_smem = (NN + 1024) * (int)sizeof(int);
    cudaFuncSetAttribute(k_scan_big, cudaFuncAttributeMaxDynamicSharedMemorySize, scan_smem);

    // ---- CSR build + weight split + output zeroing ----
    cudaMemsetAsync(cnt, 0, NN * sizeof(int));
    cudaMemsetAsync(out, 0, (size_t)out_size * sizeof(float));
    k_splitw<<<WPAIRS, DHF>>>(w1_0, w2_0, w1_r, w2_r);
    k_hist<<<(E + 255) / 256, 256>>>(erow, E);
    k_scan_big<<<1, 1024, scan_smem>>>();          // + zero cursors & BN stats
    k_scatter<<<(E + 255) / 256, 256>>>(erow, ecol, E);

    const int spmm_blocks = (NN + 7) / 8;
    const int gemm_blocks = (NN + 127) / 128;
    const int pool_blocks = (NN + BNP_ROWS - 1) / BNP_ROWS;

    // pair-row offsets into g_wpk per GEMM segment
    const int woff_g1[NLAY] = {0, 164, 228, 292};     // GEMM1 of layers 0..3
    const int woff_g2[NLAY] = {100, 356, 420, 484};   // GEMM2 of layers 0..3

    for (int l = 0; l < NLAY; l++) {
        const float *ba, *ga, *bea, *bb, *gb, *bbb;
        const float* Ain;
        int K1;
        if (l == 0) {
            k_spmm<DINF / 4><<<spmm_blocks, 256>>>(x, pooled0, eps, 0);
            Ain = pooled0; K1 = DINF;
            ba = b1_0; ga = g1_0; bea = be1_0;
            bb = b2_0; gb = gbn_0; bbb = bbn_0;
        } else {
            k_spmm<DHF / 4><<<spmm_blocks, 256>>>(h, pooled, eps, l);
            Ain = pooled; K1 = DHF;
            int o1 = (l - 1) * DHF;
            ba = b1_r + o1; ga = g1_r + o1; bea = be1_r + o1;
            bb = b2_r + o1; gb = gbn_r + o1; bbb = bbn_r + o1;
        }

        // GEMM1: plain A
        k_gemm_tc<<<gemm_blocks, 512>>>(Ain, wpk + woff_g1[l] * DHF, ba, mid, NN, K1,
                                        nullptr, nullptr, nullptr, nullptr,
                                        sumb + (2 * l) * DHF, sumsqb + (2 * l) * DHF);
        // GEMM2: BN+ReLU on A computed in-kernel from slot-2l stats
        k_gemm_tc<<<gemm_blocks, 512>>>(mid, wpk + woff_g2[l] * DHF, bb, rep, NN, DHF,
                                        ga, bea, sumb + (2 * l) * DHF, sumsqb + (2 * l) * DHF,
                                        sumb + (2 * l + 1) * DHF, sumsqb + (2 * l + 1) * DHF);

        // fused BN + ReLU + pool, chunk-parallel; h written for layers 0..2
        k_bnpool<<<pool_blocks, DHF>>>(rep, h, out, DINF + l * DHF, gb, bbb,
                                       gid, 2 * l + 1, (l < NLAY - 1) ? 1 : 0);
    }

    // pooled x -> out[:, 0:200], chunk-parallel
    k_poolx<<<pool_blocks, 256>>>(x, out, gid);
}